// round 17
// baseline (speedup 1.0000x reference)
#include <cuda_runtime.h>
#include <cuda_fp16.h>

#define ROWS  128
#define NTH   512
#define ITERS 5
#define PITCH 512                    // bytes per E row (256 fp16), chunk-swizzled

#define SZ_E     (ROWS * PITCH)      // 65536
#define OFF_EXCH SZ_E                // float[2][2][256] double-buffered = 4096
#define OFF_U    (OFF_EXCH + 4096)   // float[128]
#define OFF_W    (OFF_U + 512)       // float[256]
#define SMEM_TOTAL (OFF_W + 1024)    // 71168 B -> 3 CTAs/SM

// 16B-chunk swizzle: byte offset of chunk c in row r. c in [0,32); XOR touches low 3 bits only.
#define ECHUNK(r, c) ((((c) ^ ((r) & 7)) << 4))

__device__ __forceinline__ __half2 u2h(unsigned v) {
    __half2 h; *reinterpret_cast<unsigned*>(&h) = v; return h;
}

__global__ __launch_bounds__(NTH, 3) __cluster_dims__(2, 1, 1)
void sinkhorn_kernel(const float* __restrict__ logits,
                     const int* __restrict__ free_agents_num,
                     const int* __restrict__ tasks_num,
                     float* __restrict__ out)
{
    extern __shared__ __align__(16) unsigned char sm[];
    unsigned char* Eb = sm;
    float* exch = reinterpret_cast<float*>(sm + OFF_EXCH);  // [buf][rank][256]
    float* u    = reinterpret_cast<float*>(sm + OFF_U);
    float* w    = reinterpret_cast<float*>(sm + OFF_W);
    const float4* Wf4 = reinterpret_cast<const float4*>(w);

    const int rank = blockIdx.x & 1;
    const int b    = blockIdx.x >> 1;
    const int t    = threadIdx.x;
    const int na   = free_agents_num[b];
    const int nt   = tasks_num[b];
    const int row0 = rank * ROWS;

    const float4* __restrict__ L4 =
        reinterpret_cast<const float4*>(logits) + (size_t)b * 16384 + (size_t)rank * 8192;
    float4* __restrict__ O4 =
        reinterpret_cast<float4*>(out) + (size_t)b * 16384 + (size_t)rank * 8192;

    // Degenerate batch: both cluster CTAs share b -> both take this branch (barrier-safe).
    if (na == 0 || nt == 0) {
        float4 z = make_float4(0.f, 0.f, 0.f, 0.f);
        #pragma unroll
        for (int k = 0; k < 8192 / NTH; ++k)
            O4[t + k * NTH] = z;
        return;
    }

    const int nrl = min(max(na - row0, 0), ROWS);   // valid local rows

    // ---- Phase 1: HBM -> E(fp16, swizzled) + FUSED iteration-0 row sums (w == 1) ----
    // scr = exchange buffer 1: peer's earliest DSMEM stores hit buffer 0, and it cannot
    // issue buffer-1 stores before the it=0 cluster barrier (which we also must reach,
    // after our scr reads). No race.
    float* scr = exch + 512;
    #pragma unroll 4
    for (int k = 0; k < 8192 / NTH; ++k) {
        int idx = t + k * NTH;
        int i   = idx >> 6;                // 64 float4 per row; warp-uniform (32 | 64)
        int jf4 = idx & 63;
        int j   = jf4 << 2;
        half2 h01 = __floats2half2_rn(0.f, 0.f);
        half2 h23 = h01;
        float se = 0.f;
        if (i < nrl && j < nt) {
            float4 v = L4[idx];
            float e0 = __expf(v.x);
            float e1 = (j + 1) < nt ? __expf(v.y) : 0.f;
            float e2 = (j + 2) < nt ? __expf(v.z) : 0.f;
            float e3 = (j + 3) < nt ? __expf(v.w) : 0.f;
            h01 = __floats2half2_rn(e0, e1);
            h23 = __floats2half2_rn(e2, e3);
            se = (e0 + e1) + (e2 + e3);
        }
        uint2 pk;
        pk.x = *reinterpret_cast<unsigned*>(&h01);
        pk.y = *reinterpret_cast<unsigned*>(&h23);
        int cc = jf4 >> 1;                 // chunk 0..31
        int sub = (jf4 & 1) << 3;          // 0 or 8 bytes
        *reinterpret_cast<uint2*>(Eb + i * PITCH + ECHUNK(i, cc) + sub) = pk;
        // Warp-reduce se (all lanes same row i).
        se += __shfl_xor_sync(0xffffffffu, se, 16);
        se += __shfl_xor_sync(0xffffffffu, se, 8);
        se += __shfl_xor_sync(0xffffffffu, se, 4);
        se += __shfl_xor_sync(0xffffffffu, se, 2);
        se += __shfl_xor_sync(0xffffffffu, se, 1);
        if ((t & 31) == 0) scr[2 * i + ((t >> 5) & 1)] = se;
    }
    __syncthreads();
    if (t < 128) {
        float S = scr[2 * t] + scr[2 * t + 1];
        u[t] = (t < nrl) ? 1.0f / S : 0.f;
    }
    __syncthreads();

    const int wrp = t >> 5, l = t & 31;
    const bool cval = (8 * l) < nt;        // row-pass: my chunk has valid cols
    const int  r0w  = wrp * 8;             // row-pass: my 8 rows
    const int  nv   = min(max(nrl - r0w, 0), 8);
    const int  nb   = (nrl + 31) >> 5;     // col-pass: valid 32-row blocks (<=4)

    // DSMEM base of MY rank slot in the PEER's exchange.
    unsigned raddrE;
    {
        unsigned laddr = (unsigned)__cvta_generic_to_shared(&exch[rank * 256]);
        asm("mapa.shared::cluster.u32 %0, %1, %2;" : "=r"(raddrE) : "r"(laddr), "r"(rank ^ 1));
    }

    // 5 x (col-norm then row-norm), row-norm skipped on the last trip:
    // with the fused row-norm above = exactly 5 row + 5 col norms.
    for (int it = 0; it < ITERS; ++it) {
        const int bufo = (it & 1) * 512;

        // ---- Col pass: warp covers chunks {wrp, wrp+16}; lanes = rows (LDS.128) ----
        #pragma unroll
        for (int ci = 0; ci < 2; ++ci) {
            int c = wrp + (ci << 4);                  // warp-uniform
            bool cv2 = (8 * c) < nt;                  // warp-uniform -> uniform skip
            if (cv2) {
                float ca[8];
                #pragma unroll
                for (int j = 0; j < 8; ++j) ca[j] = 0.f;
                for (int bb = 0; bb < nb; ++bb) {
                    int r = (bb << 5) + l;
                    if (r < nrl) {
                        uint4 ev = *reinterpret_cast<const uint4*>(Eb + r * PITCH + ECHUNK(r, c));
                        float uu = u[r];
                        float2 e0 = __half22float2(u2h(ev.x));
                        float2 e1 = __half22float2(u2h(ev.y));
                        float2 e2 = __half22float2(u2h(ev.z));
                        float2 e3 = __half22float2(u2h(ev.w));
                        ca[0] = fmaf(e0.x, uu, ca[0]); ca[1] = fmaf(e0.y, uu, ca[1]);
                        ca[2] = fmaf(e1.x, uu, ca[2]); ca[3] = fmaf(e1.y, uu, ca[3]);
                        ca[4] = fmaf(e2.x, uu, ca[4]); ca[5] = fmaf(e2.y, uu, ca[5]);
                        ca[6] = fmaf(e3.x, uu, ca[6]); ca[7] = fmaf(e3.y, uu, ca[7]);
                    }
                }
                #pragma unroll
                for (int m = 1; m < 32; m <<= 1) {
                    #pragma unroll
                    for (int j = 0; j < 8; ++j)
                        ca[j] += __shfl_xor_sync(0xffffffffu, ca[j], m);
                }
                if (l < 8) {
                    int j = (c << 3) + l;
                    exch[bufo + rank * 256 + j] = ca[l];
                    unsigned ra = raddrE + (unsigned)((bufo + j) << 2);
                    asm volatile("st.shared::cluster.f32 [%0], %1;" :: "r"(ra), "f"(ca[l]) : "memory");
                }
            }
        }
        // Cluster barrier: release my DSMEM stores, acquire the peer's.
        asm volatile("barrier.cluster.arrive.aligned;" ::: "memory");
        asm volatile("barrier.cluster.wait.aligned;"   ::: "memory");

        if (t < 128) {
            int j0 = 2 * t, j1 = j0 + 1;
            float T0 = exch[bufo + j0] + exch[bufo + 256 + j0];
            float T1 = exch[bufo + j1] + exch[bufo + 256 + j1];
            w[j0] = (j0 < nt) ? 1.0f / T0 : 0.f;
            w[j1] = (j1 < nt) ? 1.0f / T1 : 0.f;
        }
        __syncthreads();

        if (it < ITERS - 1) {
            // ---- Row pass: warp covers 8 rows; lanes = chunks (LDS.128) ----
            float4 wa = Wf4[2 * l], wb = Wf4[2 * l + 1];   // w[8l..8l+7], per pass
            float sarr[8];
            #pragma unroll
            for (int rr = 0; rr < 8; ++rr) {
                float s = 0.f;
                if (rr < nv && cval) {
                    int r = r0w + rr;
                    uint4 ev = *reinterpret_cast<const uint4*>(Eb + r * PITCH + ECHUNK(r, l));
                    float2 e0 = __half22float2(u2h(ev.x));
                    float2 e1 = __half22float2(u2h(ev.y));
                    float2 e2 = __half22float2(u2h(ev.z));
                    float2 e3 = __half22float2(u2h(ev.w));
                    float sA = fmaf(e0.x, wa.x, e0.y * wa.y);
                    float sB = fmaf(e1.x, wa.z, e1.y * wa.w);
                    float sC = fmaf(e2.x, wb.x, e2.y * wb.y);
                    float sD = fmaf(e3.x, wb.z, e3.y * wb.w);
                    s = (sA + sB) + (sC + sD);
                }
                sarr[rr] = s;
            }
            #pragma unroll
            for (int m = 1; m < 32; m <<= 1) {
                #pragma unroll
                for (int rr = 0; rr < 8; ++rr)
                    sarr[rr] += __shfl_xor_sync(0xffffffffu, sarr[rr], m);
            }
            if (l < 8) {
                int r = r0w + l;
                u[r] = (r < nrl) ? 1.0f / sarr[l] : 0.f;
            }
            __syncthreads();
        }
    }

    // ---- Phase 3: out = E * u_i * w_j * exp(1e-6); thread = (row, chunk l) ----
    {
        const float C = 1.0000010000005f;
        float4 wa = Wf4[2 * l], wb = Wf4[2 * l + 1];       // final w[8l..8l+7]
        #pragma unroll 2
        for (int k = 0; k < 8; ++k) {
            int row = wrp + (k << 4);                      // warp-uniform, < 128
            if (row < nrl) {
                uint4 ev = *reinterpret_cast<const uint4*>(Eb + row * PITCH + ECHUNK(row, l));
                float ui = u[row] * C;
                float2 e0 = __half22float2(u2h(ev.x));
                float2 e1 = __half22float2(u2h(ev.y));
                float2 e2 = __half22float2(u2h(ev.z));
                float2 e3 = __half22float2(u2h(ev.w));
                float4 r0 = make_float4(e0.x * ui * wa.x, e0.y * ui * wa.y,
                                        e1.x * ui * wa.z, e1.y * ui * wa.w);
                float4 r1 = make_float4(e2.x * ui * wb.x, e2.y * ui * wb.y,
                                        e3.x * ui * wb.z, e3.y * ui * wb.w);
                O4[row * 64 + 2 * l]     = r0;
                O4[row * 64 + 2 * l + 1] = r1;
            } else {
                float4 z = make_float4(0.f, 0.f, 0.f, 0.f);
                O4[row * 64 + 2 * l]     = z;
                O4[row * 64 + 2 * l + 1] = z;
            }
        }
    }
}

extern "C" void kernel_launch(void* const* d_in, const int* in_sizes, int n_in,
                              void* d_out, int out_size)
{
    const float* logits = (const float*)d_in[0];
    const int*   agents = (const int*)d_in[1];
    const int*   tasks  = (const int*)d_in[2];
    float*       out    = (float*)d_out;
    const int B = in_sizes[1];

    cudaFuncSetAttribute(sinkhorn_kernel,
                         cudaFuncAttributeMaxDynamicSharedMemorySize, SMEM_TOTAL);

    sinkhorn_kernel<<<2 * B, NTH, SMEM_TOTAL>>>(logits, agents, tasks, out);
}